// round 1
// baseline (speedup 1.0000x reference)
#include <cuda_runtime.h>
#include <math.h>

#define T_SEQ 4096
#define C_DIM 2048
#define KV_DIM 512
#define NH 16
#define NKV 4
#define HD 128
#define HALF 64
#define WIN 64

// Scratch (no runtime allocation allowed)
__device__ float g_Q[T_SEQ * C_DIM];
__device__ float g_K[T_SEQ * KV_DIM];
__device__ float g_V[T_SEQ * KV_DIM];
__device__ float g_AO[T_SEQ * C_DIM];

// ---------------------------------------------------------------------------
// SGEMM: C[M,N] = A[M,K] @ B[K,N], all row-major, fp32.
// 128x128 tile, BK=8, 256 threads, 8x8 per thread. M,N,K multiples of 128/8.
// ---------------------------------------------------------------------------
__global__ void __launch_bounds__(256) sgemm128(const float* __restrict__ A,
                                                const float* __restrict__ B,
                                                float* __restrict__ C,
                                                int M, int N, int K) {
    __shared__ float As[8][128];
    __shared__ float Bs[8][128];
    const int tid  = threadIdx.x;
    const int bm   = blockIdx.y * 128;
    const int bn   = blockIdx.x * 128;
    const int arow = tid >> 1;          // 0..127
    const int acol = (tid & 1) << 2;    // 0 or 4
    const int brow = tid >> 5;          // 0..7
    const int bcol = (tid & 31) << 2;   // 0..124
    const int ty   = tid >> 4;          // 0..15
    const int tx   = tid & 15;          // 0..15

    const float* Aptr = A + (size_t)(bm + arow) * K + acol;
    const float* Bptr = B + (size_t)brow * N + bn + bcol;

    float acc[8][8];
#pragma unroll
    for (int i = 0; i < 8; i++)
#pragma unroll
        for (int j = 0; j < 8; j++) acc[i][j] = 0.f;

    for (int k0 = 0; k0 < K; k0 += 8) {
        float4 a = *(const float4*)(Aptr + k0);
        As[acol + 0][arow] = a.x;
        As[acol + 1][arow] = a.y;
        As[acol + 2][arow] = a.z;
        As[acol + 3][arow] = a.w;
        *(float4*)&Bs[brow][bcol] = *(const float4*)(Bptr + (size_t)k0 * N);
        __syncthreads();
#pragma unroll
        for (int k = 0; k < 8; k++) {
            float4 a0 = *(const float4*)&As[k][ty * 8];
            float4 a1 = *(const float4*)&As[k][ty * 8 + 4];
            float4 b0 = *(const float4*)&Bs[k][tx * 8];
            float4 b1 = *(const float4*)&Bs[k][tx * 8 + 4];
            float av[8] = {a0.x, a0.y, a0.z, a0.w, a1.x, a1.y, a1.z, a1.w};
            float bv[8] = {b0.x, b0.y, b0.z, b0.w, b1.x, b1.y, b1.z, b1.w};
#pragma unroll
            for (int i = 0; i < 8; i++)
#pragma unroll
                for (int j = 0; j < 8; j++)
                    acc[i][j] = fmaf(av[i], bv[j], acc[i][j]);
        }
        __syncthreads();
    }
#pragma unroll
    for (int i = 0; i < 8; i++) {
        float* Crow = C + (size_t)(bm + ty * 8 + i) * N + bn + tx * 8;
        *(float4*)Crow       = make_float4(acc[i][0], acc[i][1], acc[i][2], acc[i][3]);
        *(float4*)(Crow + 4) = make_float4(acc[i][4], acc[i][5], acc[i][6], acc[i][7]);
    }
}

// ---------------------------------------------------------------------------
// RoPE in-place: data is [T, nheads, 128]; rotate pairs (2j, 2j+1), j<64.
// freq = t * theta^(-j/64), matches jnp fp32 reference within tolerance.
// ---------------------------------------------------------------------------
__global__ void rope_kernel(float* __restrict__ data, int nheads, int total) {
    int p = blockIdx.x * blockDim.x + threadIdx.x;
    if (p >= total) return;
    int j = p % HALF;
    int h = (p / HALF) % nheads;
    int t = p / (HALF * nheads);
    float inv = powf(10000.0f, -(float)j / (float)HALF);
    float f = (float)t * inv;
    float s, c;
    sincosf(f, &s, &c);
    int base = (t * nheads + h) * HD + 2 * j;
    float xr = data[base];
    float xi = data[base + 1];
    data[base]     = xr * c - xi * s;
    data[base + 1] = xr * s + xi * c;
}

// ---------------------------------------------------------------------------
// Sliding-window attention, online softmax. One warp per (query, head).
// Q,O: [T, 16*128]; K,V: [T, 4*128]. Band |t-s| <= 64. sink==const -> cancels.
// ---------------------------------------------------------------------------
__global__ void __launch_bounds__(256) attn_kernel(const float* __restrict__ Q,
                                                   const float* __restrict__ K,
                                                   const float* __restrict__ V,
                                                   float* __restrict__ O) {
    const int warp = threadIdx.x >> 5;
    const int lane = threadIdx.x & 31;
    const int t = blockIdx.x * 8 + warp;
    const int h = blockIdx.y;
    const int kh = h >> 2;  // n_rep = 4
    const float scale = 0.08838834764831845f;  // 128^-0.5

    const float* qp = Q + (size_t)t * C_DIM + h * HD + lane;
    const float q0 = qp[0], q1 = qp[32], q2 = qp[64], q3 = qp[96];

    int s0 = t - WIN; if (s0 < 0) s0 = 0;
    int s1 = t + WIN; if (s1 > T_SEQ - 1) s1 = T_SEQ - 1;

    float m = -1e30f, l = 0.f;
    float a0 = 0.f, a1 = 0.f, a2 = 0.f, a3 = 0.f;

    for (int s = s0; s <= s1; s++) {
        const float* kp = K + (size_t)s * KV_DIM + kh * HD + lane;
        float d = q0 * kp[0] + q1 * kp[32] + q2 * kp[64] + q3 * kp[96];
#pragma unroll
        for (int o = 16; o > 0; o >>= 1) d += __shfl_xor_sync(0xffffffffu, d, o);
        d *= scale;
        float mn = fmaxf(m, d);
        float corr = __expf(m - mn);
        float p = __expf(d - mn);
        m = mn;
        l = l * corr + p;
        const float* vp = V + (size_t)s * KV_DIM + kh * HD + lane;
        a0 = a0 * corr + p * vp[0];
        a1 = a1 * corr + p * vp[32];
        a2 = a2 * corr + p * vp[64];
        a3 = a3 * corr + p * vp[96];
    }
    float linv = 1.f / l;
    float* op = O + (size_t)t * C_DIM + h * HD + lane;
    op[0]  = a0 * linv;
    op[32] = a1 * linv;
    op[64] = a2 * linv;
    op[96] = a3 * linv;
}

// ---------------------------------------------------------------------------
extern "C" void kernel_launch(void* const* d_in, const int* in_sizes, int n_in,
                              void* d_out, int out_size) {
    const float* x  = (const float*)d_in[0];
    const float* wq = (const float*)d_in[1];
    const float* wk = (const float*)d_in[2];
    const float* wv = (const float*)d_in[3];
    const float* wo = (const float*)d_in[4];
    // d_in[5] = sink: per-(b,h) constant added to every score in a softmax row
    // -> cancels exactly in softmax; ignored.
    float* out = (float*)d_out;

    float *Q, *Kp, *Vp, *AO;
    cudaGetSymbolAddress((void**)&Q,  g_Q);
    cudaGetSymbolAddress((void**)&Kp, g_K);
    cudaGetSymbolAddress((void**)&Vp, g_V);
    cudaGetSymbolAddress((void**)&AO, g_AO);

    dim3 thr(256);
    sgemm128<<<dim3(C_DIM / 128, T_SEQ / 128), thr>>>(x, wq, Q,  T_SEQ, C_DIM,  C_DIM);
    sgemm128<<<dim3(KV_DIM / 128, T_SEQ / 128), thr>>>(x, wk, Kp, T_SEQ, KV_DIM, C_DIM);
    sgemm128<<<dim3(KV_DIM / 128, T_SEQ / 128), thr>>>(x, wv, Vp, T_SEQ, KV_DIM, C_DIM);

    int ropeQ = T_SEQ * NH * HALF;
    rope_kernel<<<(ropeQ + 255) / 256, 256>>>(Q, NH, ropeQ);
    int ropeK = T_SEQ * NKV * HALF;
    rope_kernel<<<(ropeK + 255) / 256, 256>>>(Kp, NKV, ropeK);

    attn_kernel<<<dim3(T_SEQ / 8, NH), 256>>>(Q, Kp, Vp, AO);

    sgemm128<<<dim3(C_DIM / 128, T_SEQ / 128), thr>>>(AO, wo, out, T_SEQ, C_DIM, C_DIM);
}

// round 2
// speedup vs baseline: 2.5048x; 2.5048x over previous
#include <cuda_runtime.h>
#include <math.h>
#include <stdint.h>

#define T_SEQ 4096
#define C_DIM 2048
#define KV_DIM 512
#define NH 16
#define NKV 4
#define HD 128
#define HALF 64
#define WIN 64

// Scratch (no runtime allocation allowed)
__device__ float g_Q[T_SEQ * C_DIM];
__device__ float g_K[T_SEQ * KV_DIM];
__device__ float g_V[T_SEQ * KV_DIM];
__device__ float g_AO[T_SEQ * C_DIM];

// ---------------------------------------------------------------------------
// TF32 tensor-core GEMM: C[M,N] = A[M,K] @ B[K,N], row-major fp32 in/out.
// 128x128x32 tiles, 256 threads (8 warps, 2x4), warp tile 64x32,
// mma.sync.m16n8k8.tf32. Double-buffered smem; inputs cvt.rna -> tf32.
// M,N multiples of 128; K multiple of 32.
// ---------------------------------------------------------------------------
#define SA 36    // As row stride (floats), pad for conflict-free frag loads
#define SB 132   // Bs row stride
#define BUF_FLOATS (128 * SA + 32 * SB)   // 4608 + 4224 = 8832

__device__ __forceinline__ uint32_t f2tf32(float f) {
    uint32_t u;
    asm("cvt.rna.tf32.f32 %0, %1;" : "=r"(u) : "f"(f));
    return u;
}

__device__ __forceinline__ void mma_tf32(float c[4], const uint32_t a[4],
                                         const uint32_t b[2]) {
    asm volatile(
        "mma.sync.aligned.m16n8k8.row.col.f32.tf32.tf32.f32 "
        "{%0,%1,%2,%3}, {%4,%5,%6,%7}, {%8,%9}, {%0,%1,%2,%3};\n"
        : "+f"(c[0]), "+f"(c[1]), "+f"(c[2]), "+f"(c[3])
        : "r"(a[0]), "r"(a[1]), "r"(a[2]), "r"(a[3]), "r"(b[0]), "r"(b[1]));
}

__global__ void __launch_bounds__(256, 2) gemm_tf32(const float* __restrict__ A,
                                                    const float* __restrict__ B,
                                                    float* __restrict__ C,
                                                    int M, int N, int K) {
    extern __shared__ float smem[];
    const int tid = threadIdx.x;
    const int bm = blockIdx.y * 128;
    const int bn = blockIdx.x * 128;
    const int warp = tid >> 5;
    const int lane = tid & 31;
    const int wm = warp >> 2;       // 0..1
    const int wn = warp & 3;        // 0..3
    const int g  = lane >> 2;       // groupID 0..7
    const int tg = lane & 3;        // threadID_in_group 0..3

    // global load indices
    const int arow = tid >> 3;             // 0..31, +32 per pass (4 passes)
    const int acol = (tid & 7) << 2;       // 0..28
    const int brow = tid >> 5;             // 0..7, +8 per pass
    const int bcol = (tid & 31) << 2;      // 0..124

    const int KT = K >> 5;  // K tiles of 32

    float acc[4][4][4];
#pragma unroll
    for (int i = 0; i < 4; i++)
#pragma unroll
        for (int j = 0; j < 4; j++)
#pragma unroll
            for (int r = 0; r < 4; r++) acc[i][j][r] = 0.f;

    float4 ra[4], rb[4];

    // prologue: load tile 0
#pragma unroll
    for (int p = 0; p < 4; p++)
        ra[p] = *(const float4*)(A + (size_t)(bm + arow + p * 32) * K + acol);
#pragma unroll
    for (int p = 0; p < 4; p++)
        rb[p] = *(const float4*)(B + (size_t)(brow + p * 8) * N + bn + bcol);
    {
        float* As = smem;
        float* Bs = smem + 128 * SA;
        uint32_t* asu = (uint32_t*)As;
        uint32_t* bsu = (uint32_t*)Bs;
#pragma unroll
        for (int p = 0; p < 4; p++) {
            uint4 v = make_uint4(f2tf32(ra[p].x), f2tf32(ra[p].y),
                                 f2tf32(ra[p].z), f2tf32(ra[p].w));
            *(uint4*)&asu[(arow + p * 32) * SA + acol] = v;
            uint4 w = make_uint4(f2tf32(rb[p].x), f2tf32(rb[p].y),
                                 f2tf32(rb[p].z), f2tf32(rb[p].w));
            *(uint4*)&bsu[(brow + p * 8) * SB + bcol] = w;
        }
    }
    __syncthreads();

    for (int kt = 0; kt < KT; kt++) {
        const uint32_t* su = (const uint32_t*)(smem + (kt & 1) * BUF_FLOATS);
        const uint32_t* bu = su + 128 * SA;

        if (kt + 1 < KT) {
            const float* Ab = A + (size_t)(kt + 1) * 32;
#pragma unroll
            for (int p = 0; p < 4; p++)
                ra[p] = *(const float4*)(Ab + (size_t)(bm + arow + p * 32) * K + acol);
            const float* Bb = B + (size_t)(kt + 1) * 32 * N;
#pragma unroll
            for (int p = 0; p < 4; p++)
                rb[p] = *(const float4*)(Bb + (size_t)(brow + p * 8) * N + bn + bcol);
        }

#pragma unroll
        for (int ks = 0; ks < 4; ks++) {
            const int kk = ks * 8 + tg;
            uint32_t af[4][4], bf[4][2];
#pragma unroll
            for (int i = 0; i < 4; i++) {
                int r0 = (wm * 64 + i * 16 + g) * SA;
                af[i][0] = su[r0 + kk];
                af[i][1] = su[r0 + 8 * SA + kk];
                af[i][2] = su[r0 + kk + 4];
                af[i][3] = su[r0 + 8 * SA + kk + 4];
            }
#pragma unroll
            for (int j = 0; j < 4; j++) {
                int c0 = wn * 32 + j * 8 + g;
                bf[j][0] = bu[(ks * 8 + tg) * SB + c0];
                bf[j][1] = bu[(ks * 8 + tg + 4) * SB + c0];
            }
#pragma unroll
            for (int i = 0; i < 4; i++)
#pragma unroll
                for (int j = 0; j < 4; j++) mma_tf32(acc[i][j], af[i], bf[j]);
        }

        if (kt + 1 < KT) {
            uint32_t* asu = (uint32_t*)(smem + ((kt + 1) & 1) * BUF_FLOATS);
            uint32_t* bsu = asu + 128 * SA;
#pragma unroll
            for (int p = 0; p < 4; p++) {
                uint4 v = make_uint4(f2tf32(ra[p].x), f2tf32(ra[p].y),
                                     f2tf32(ra[p].z), f2tf32(ra[p].w));
                *(uint4*)&asu[(arow + p * 32) * SA + acol] = v;
                uint4 w = make_uint4(f2tf32(rb[p].x), f2tf32(rb[p].y),
                                     f2tf32(rb[p].z), f2tf32(rb[p].w));
                *(uint4*)&bsu[(brow + p * 8) * SB + bcol] = w;
            }
        }
        __syncthreads();
    }

    // epilogue: c0,c1 at (row, 2tg), (row, 2tg+1); c2,c3 at row+8
#pragma unroll
    for (int i = 0; i < 4; i++) {
#pragma unroll
        for (int j = 0; j < 4; j++) {
            int row = bm + wm * 64 + i * 16 + g;
            int col = bn + wn * 32 + j * 8 + 2 * tg;
            *(float2*)(C + (size_t)row * N + col) =
                make_float2(acc[i][j][0], acc[i][j][1]);
            *(float2*)(C + (size_t)(row + 8) * N + col) =
                make_float2(acc[i][j][2], acc[i][j][3]);
        }
    }
}

// ---------------------------------------------------------------------------
// RoPE in-place: data is [T, nheads, 128]; rotate pairs (2j, 2j+1), j<64.
// ---------------------------------------------------------------------------
__global__ void rope_kernel(float* __restrict__ data, int nheads, int total) {
    int p = blockIdx.x * blockDim.x + threadIdx.x;
    if (p >= total) return;
    int j = p % HALF;
    int h = (p / HALF) % nheads;
    int t = p / (HALF * nheads);
    float inv = powf(10000.0f, -(float)j / (float)HALF);
    float f = (float)t * inv;
    float s, c;
    sincosf(f, &s, &c);
    int base = (t * nheads + h) * HD + 2 * j;
    float xr = data[base];
    float xi = data[base + 1];
    data[base]     = xr * c - xi * s;
    data[base + 1] = xr * s + xi * c;
}

// ---------------------------------------------------------------------------
// Sliding-window attention: one warp handles 4 adjacent queries of one head,
// sharing each K/V float4 load. Branchy online softmax (rescale only on new
// max). sink is per-(b,h,q)-row constant -> cancels in softmax; ignored.
// ---------------------------------------------------------------------------
__global__ void __launch_bounds__(256) attn_kernel(const float* __restrict__ Q,
                                                   const float* __restrict__ K,
                                                   const float* __restrict__ V,
                                                   float* __restrict__ O) {
    const int warp = threadIdx.x >> 5;
    const int lane = threadIdx.x & 31;
    const int tq = (blockIdx.x * 8 + warp) * 4;
    const int h = blockIdx.y;
    const int kh = h >> 2;  // n_rep = 4
    const float scale = 0.08838834764831845f;  // 128^-0.5

    float4 q[4];
#pragma unroll
    for (int i = 0; i < 4; i++)
        q[i] = *(const float4*)(Q + (size_t)(tq + i) * C_DIM + h * HD + lane * 4);

    float m[4] = {-1e30f, -1e30f, -1e30f, -1e30f};
    float l[4] = {0.f, 0.f, 0.f, 0.f};
    float4 a[4];
#pragma unroll
    for (int i = 0; i < 4; i++) a[i] = make_float4(0.f, 0.f, 0.f, 0.f);

    int s0 = tq - WIN;      if (s0 < 0) s0 = 0;
    int s1 = tq + 3 + WIN;  if (s1 > T_SEQ - 1) s1 = T_SEQ - 1;

    for (int s = s0; s <= s1; s++) {
        float4 kv = *(const float4*)(K + (size_t)s * KV_DIM + kh * HD + lane * 4);
        float4 vv = *(const float4*)(V + (size_t)s * KV_DIM + kh * HD + lane * 4);
#pragma unroll
        for (int i = 0; i < 4; i++) {
            int t = tq + i;
            if (s < t - WIN || s > t + WIN) continue;  // warp-uniform
            float d = q[i].x * kv.x + q[i].y * kv.y + q[i].z * kv.z + q[i].w * kv.w;
#pragma unroll
            for (int o = 16; o > 0; o >>= 1) d += __shfl_xor_sync(0xffffffffu, d, o);
            d *= scale;
            if (d <= m[i]) {
                float p = __expf(d - m[i]);
                l[i] += p;
                a[i].x += p * vv.x;
                a[i].y += p * vv.y;
                a[i].z += p * vv.z;
                a[i].w += p * vv.w;
            } else {
                float corr = __expf(m[i] - d);
                m[i] = d;
                l[i] = l[i] * corr + 1.f;
                a[i].x = a[i].x * corr + vv.x;
                a[i].y = a[i].y * corr + vv.y;
                a[i].z = a[i].z * corr + vv.z;
                a[i].w = a[i].w * corr + vv.w;
            }
        }
    }
#pragma unroll
    for (int i = 0; i < 4; i++) {
        float inv = 1.f / l[i];
        *(float4*)(O + (size_t)(tq + i) * C_DIM + h * HD + lane * 4) =
            make_float4(a[i].x * inv, a[i].y * inv, a[i].z * inv, a[i].w * inv);
    }
}

// ---------------------------------------------------------------------------
extern "C" void kernel_launch(void* const* d_in, const int* in_sizes, int n_in,
                              void* d_out, int out_size) {
    const float* x  = (const float*)d_in[0];
    const float* wq = (const float*)d_in[1];
    const float* wk = (const float*)d_in[2];
    const float* wv = (const float*)d_in[3];
    const float* wo = (const float*)d_in[4];
    // d_in[5] = sink: constant per softmax row -> cancels; ignored.
    float* out = (float*)d_out;

    float *Q, *Kp, *Vp, *AO;
    cudaGetSymbolAddress((void**)&Q,  g_Q);
    cudaGetSymbolAddress((void**)&Kp, g_K);
    cudaGetSymbolAddress((void**)&Vp, g_V);
    cudaGetSymbolAddress((void**)&AO, g_AO);

    const int smemB = BUF_FLOATS * 2 * sizeof(float);  // 70656
    cudaFuncSetAttribute(gemm_tf32, cudaFuncAttributeMaxDynamicSharedMemorySize,
                         smemB);

    gemm_tf32<<<dim3(C_DIM / 128, T_SEQ / 128), 256, smemB>>>(x, wq, Q,  T_SEQ, C_DIM,  C_DIM);
    gemm_tf32<<<dim3(KV_DIM / 128, T_SEQ / 128), 256, smemB>>>(x, wk, Kp, T_SEQ, KV_DIM, C_DIM);
    gemm_tf32<<<dim3(KV_DIM / 128, T_SEQ / 128), 256, smemB>>>(x, wv, Vp, T_SEQ, KV_DIM, C_DIM);

    int ropeQ = T_SEQ * NH * HALF;
    rope_kernel<<<(ropeQ + 255) / 256, 256>>>(Q, NH, ropeQ);
    int ropeK = T_SEQ * NKV * HALF;
    rope_kernel<<<(ropeK + 255) / 256, 256>>>(Kp, NKV, ropeK);

    attn_kernel<<<dim3(T_SEQ / 32, NH), 256>>>(Q, Kp, Vp, AO);

    gemm_tf32<<<dim3(C_DIM / 128, T_SEQ / 128), 256, smemB>>>(AO, wo, out, T_SEQ, C_DIM, C_DIM);
}